// round 6
// baseline (speedup 1.0000x reference)
#include <cuda_runtime.h>
#include <cuda_bf16.h>
#include <stdint.h>

#define N_NODES 50000
#define N_EDGES 800000
#define N_GRAPHS 256
#define DIN0 32
#define HID 96
#define BN_EPS 1e-5f

// ---------------- device scratch (static, allowed) ----------------
__device__ float g_h[(size_t)N_NODES * HID];
__device__ float g_agg[(size_t)N_NODES * HID];
__device__ float g_z[(size_t)N_NODES * HID];
__device__ int   g_deg[N_NODES];
__device__ int   g_cnt[N_NODES];
__device__ int   g_rowptr[N_NODES + 1];
__device__ int   g_col[N_EDGES];

// ---------------- CSR build ----------------
__global__ void zero_counts_kernel() {
    int i = blockIdx.x * blockDim.x + threadIdx.x;
    if (i < N_NODES) { g_deg[i] = 0; g_cnt[i] = 0; }
}

__global__ void hist_kernel(const int* __restrict__ ei) {
    int e = blockIdx.x * blockDim.x + threadIdx.x;
    if (e < N_EDGES) atomicAdd(&g_deg[ei[N_EDGES + e]], 1);
}

// single-block inclusive scan over g_deg -> g_rowptr (exclusive form)
__global__ void scan_kernel() {
    __shared__ int s[1024];
    const int tid = threadIdx.x;
    int carry = 0;
    const int nchunk = (N_NODES + 1023) / 1024;
    for (int c = 0; c < nchunk; c++) {
        int i = c * 1024 + tid;
        int v = (i < N_NODES) ? g_deg[i] : 0;
        s[tid] = v;
        __syncthreads();
        #pragma unroll
        for (int off = 1; off < 1024; off <<= 1) {
            int t = (tid >= off) ? s[tid - off] : 0;
            __syncthreads();
            s[tid] += t;
            __syncthreads();
        }
        if (i < N_NODES) g_rowptr[i + 1] = carry + s[tid];
        carry += s[1023];
        __syncthreads();
    }
    if (tid == 0) g_rowptr[0] = 0;
}

__global__ void fill_kernel(const int* __restrict__ ei) {
    int e = blockIdx.x * blockDim.x + threadIdx.x;
    if (e >= N_EDGES) return;
    int s = ei[e];
    int d = ei[N_EDGES + e];
    int pos = g_rowptr[d] + atomicAdd(&g_cnt[d], 1);
    g_col[pos] = s;
}

// ---------------- gather aggregation: agg[n] = h[n] + sum_{j in N(n)} h[j] ----
// warp per node; lane owns cols {lane, lane+32, lane+64} (< DIN)
template<int DIN>
__global__ void __launch_bounds__(256) gather_kernel(const float* __restrict__ h,
                                                     float* __restrict__ agg) {
    int warp = (blockIdx.x * blockDim.x + threadIdx.x) >> 5;
    int lane = threadIdx.x & 31;
    if (warp >= N_NODES) return;
    int n = warp;
    int start = g_rowptr[n];
    int end   = g_rowptr[n + 1];

    const float* hn = h + (size_t)n * DIN;
    float a0 = hn[lane];
    float a1 = (DIN > 32) ? hn[lane + 32] : 0.f;
    float a2 = (DIN > 64) ? hn[lane + 64] : 0.f;

    int e = start;
    #pragma unroll 1
    for (; e + 4 <= end; e += 4) {
        int s0 = g_col[e], s1 = g_col[e+1], s2 = g_col[e+2], s3 = g_col[e+3];
        const float* p0 = h + (size_t)s0 * DIN;
        const float* p1 = h + (size_t)s1 * DIN;
        const float* p2 = h + (size_t)s2 * DIN;
        const float* p3 = h + (size_t)s3 * DIN;
        a0 += p0[lane] + p1[lane] + p2[lane] + p3[lane];
        if (DIN > 32) a1 += p0[lane+32] + p1[lane+32] + p2[lane+32] + p3[lane+32];
        if (DIN > 64) a2 += p0[lane+64] + p1[lane+64] + p2[lane+64] + p3[lane+64];
    }
    for (; e < end; e++) {
        const float* p = h + (size_t)g_col[e] * DIN;
        a0 += p[lane];
        if (DIN > 32) a1 += p[lane + 32];
        if (DIN > 64) a2 += p[lane + 64];
    }

    float* an = agg + (size_t)n * DIN;
    an[lane] = a0;
    if (DIN > 32) an[lane + 32] = a1;
    if (DIN > 64) an[lane + 64] = a2;
}

// ---------------- GEMM: out = epilogue(A[N x DIN] @ W[DIN x 96]) ----------------
template<int DIN, bool HAS_BN>
__global__ void __launch_bounds__(192, 5) gemm_kernel(
    const float* __restrict__ A, const float* __restrict__ W,
    const float* __restrict__ bias,
    const float* __restrict__ gamma, const float* __restrict__ beta,
    const float* __restrict__ rmean, const float* __restrict__ rvar,
    float* __restrict__ out)
{
    constexpr int H = HID;
    constexpr int BM = 64;
    constexpr int KT = 16;
    constexpr int NKT = DIN / KT;
    constexpr int NV = BM * (KT / 4);
    __shared__ float Ws[DIN * H];
    __shared__ float As[2][KT][BM];

    const int tid = threadIdx.x;
    const int row0 = blockIdx.x * BM;

    for (int i = tid; i < DIN * H / 4; i += 192)
        ((float4*)Ws)[i] = ((const float4*)W)[i];

    const int row_t = tid & 15;
    const int col_t = tid >> 4;
    const int r0 = row_t * 4;
    const int c0 = col_t * 8;

    float acc[4][8];
    #pragma unroll
    for (int i = 0; i < 4; i++)
        #pragma unroll
        for (int j = 0; j < 8; j++) acc[i][j] = 0.f;

    float4 vst[2];

    #pragma unroll
    for (int it = 0; it < 2; it++) {
        int i = tid + it * 192;
        if (i < NV) {
            int r = i & 63, kv = i >> 6;
            int gr = row0 + r;
            vst[it] = (gr < N_NODES)
                ? *(const float4*)(A + (size_t)gr * DIN + kv * 4)
                : make_float4(0.f, 0.f, 0.f, 0.f);
        }
    }
    #pragma unroll
    for (int it = 0; it < 2; it++) {
        int i = tid + it * 192;
        if (i < NV) {
            int r = i & 63, kv = i >> 6;
            As[0][kv * 4 + 0][r] = vst[it].x;
            As[0][kv * 4 + 1][r] = vst[it].y;
            As[0][kv * 4 + 2][r] = vst[it].z;
            As[0][kv * 4 + 3][r] = vst[it].w;
        }
    }
    __syncthreads();

    int buf = 0;
    for (int kt = 0; kt < NKT; kt++) {
        if (kt + 1 < NKT) {
            #pragma unroll
            for (int it = 0; it < 2; it++) {
                int i = tid + it * 192;
                if (i < NV) {
                    int r = i & 63, kv = i >> 6;
                    int gr = row0 + r;
                    vst[it] = (gr < N_NODES)
                        ? *(const float4*)(A + (size_t)gr * DIN + (kt + 1) * KT + kv * 4)
                        : make_float4(0.f, 0.f, 0.f, 0.f);
                }
            }
        }

        #pragma unroll
        for (int kk = 0; kk < KT; kk++) {
            float4 a4 = *(const float4*)&As[buf][kk][r0];
            const float4* wr = (const float4*)&Ws[(kt * KT + kk) * H + c0];
            float4 w0 = wr[0], w1 = wr[1];
            float a[4] = {a4.x, a4.y, a4.z, a4.w};
            float w[8] = {w0.x, w0.y, w0.z, w0.w, w1.x, w1.y, w1.z, w1.w};
            #pragma unroll
            for (int i = 0; i < 4; i++)
                #pragma unroll
                for (int j = 0; j < 8; j++)
                    acc[i][j] = fmaf(a[i], w[j], acc[i][j]);
        }

        if (kt + 1 < NKT) {
            #pragma unroll
            for (int it = 0; it < 2; it++) {
                int i = tid + it * 192;
                if (i < NV) {
                    int r = i & 63, kv = i >> 6;
                    As[buf ^ 1][kv * 4 + 0][r] = vst[it].x;
                    As[buf ^ 1][kv * 4 + 1][r] = vst[it].y;
                    As[buf ^ 1][kv * 4 + 2][r] = vst[it].z;
                    As[buf ^ 1][kv * 4 + 3][r] = vst[it].w;
                }
            }
            __syncthreads();
        }
        buf ^= 1;
    }

    float sc[8], sh[8];
    #pragma unroll
    for (int j = 0; j < 8; j++) {
        int c = c0 + j;
        if (HAS_BN) {
            float s = gamma[c] * rsqrtf(rvar[c] + BN_EPS);
            sc[j] = s;
            sh[j] = (bias[c] - rmean[c]) * s + beta[c];
        } else {
            sc[j] = 1.f;
            sh[j] = bias[c];
        }
    }
    #pragma unroll
    for (int i = 0; i < 4; i++) {
        int gr = row0 + r0 + i;
        if (gr < N_NODES) {
            float v[8];
            #pragma unroll
            for (int j = 0; j < 8; j++)
                v[j] = fmaxf(fmaf(acc[i][j], sc[j], sh[j]), 0.f);
            *(float4*)(out + (size_t)gr * H + c0)     = make_float4(v[0], v[1], v[2], v[3]);
            *(float4*)(out + (size_t)gr * H + c0 + 4) = make_float4(v[4], v[5], v[6], v[7]);
        }
    }
}

// ---------------- pooling (batch is sorted -> segment sums, no atomics) -------
__global__ void __launch_bounds__(96) pool_kernel(const int* __restrict__ batch,
                                                  float* __restrict__ pool) {
    int b = blockIdx.x;          // graph id
    int c = threadIdx.x;         // column 0..95
    // binary search: first index with batch[i] >= b, and >= b+1
    int lo = 0, hi = N_NODES;
    while (lo < hi) { int m = (lo + hi) >> 1; if (batch[m] < b) lo = m + 1; else hi = m; }
    int start = lo;
    hi = N_NODES;
    while (lo < hi) { int m = (lo + hi) >> 1; if (batch[m] < b + 1) lo = m + 1; else hi = m; }
    int end = lo;

    float acc = 0.f;
    for (int n = start; n < end; n++)
        acc += g_h[(size_t)n * HID + c];
    pool[b * HID + c] = acc;
}

__global__ void head_kernel(const int* __restrict__ r_target,
                            const float* __restrict__ head_w,
                            const float* __restrict__ head_b,
                            const float* __restrict__ pool,
                            float* __restrict__ out) {
    int b = threadIdx.x;
    if (b >= N_GRAPHS) return;
    int t = r_target[b];
    const float4* w = (const float4*)(head_w + (size_t)t * HID);
    const float4* p = (const float4*)(pool + (size_t)b * HID);
    float acc = 0.f;
    #pragma unroll
    for (int k = 0; k < HID / 4; k++) {
        float4 wv = w[k], pv = p[k];
        acc = fmaf(pv.x, wv.x, acc);
        acc = fmaf(pv.y, wv.y, acc);
        acc = fmaf(pv.z, wv.z, acc);
        acc = fmaf(pv.w, wv.w, acc);
    }
    out[b] = acc + head_b[t];
}

__device__ float g_pool[N_GRAPHS * HID];

// ---------------- launch ----------------
extern "C" void kernel_launch(void* const* d_in, const int* in_sizes, int n_in,
                              void* d_out, int out_size) {
    const float* x    = (const float*)d_in[0];
    const int*   ei   = (const int*)d_in[1];
    const int*   bat  = (const int*)d_in[2];
    const int*   rtg  = (const int*)d_in[3];

    const float* w_in[3]  = {(const float*)d_in[4],  (const float*)d_in[12], (const float*)d_in[20]};
    const float* b_in[3]  = {(const float*)d_in[5],  (const float*)d_in[13], (const float*)d_in[21]};
    const float* gam[3]   = {(const float*)d_in[6],  (const float*)d_in[14], (const float*)d_in[22]};
    const float* bet[3]   = {(const float*)d_in[7],  (const float*)d_in[15], (const float*)d_in[23]};
    const float* rme[3]   = {(const float*)d_in[8],  (const float*)d_in[16], (const float*)d_in[24]};
    const float* rva[3]   = {(const float*)d_in[9],  (const float*)d_in[17], (const float*)d_in[25]};
    const float* w_out[3] = {(const float*)d_in[10], (const float*)d_in[18], (const float*)d_in[26]};
    const float* b_out[3] = {(const float*)d_in[11], (const float*)d_in[19], (const float*)d_in[27]};
    const float* head_w   = (const float*)d_in[28];
    const float* head_b   = (const float*)d_in[29];
    float* out = (float*)d_out;

    float *hbuf, *aggbuf, *zbuf, *poolbuf;
    cudaGetSymbolAddress((void**)&hbuf, g_h);
    cudaGetSymbolAddress((void**)&aggbuf, g_agg);
    cudaGetSymbolAddress((void**)&zbuf, g_z);
    cudaGetSymbolAddress((void**)&poolbuf, g_pool);

    const int TB = 256;
    const int GB = 192;
    const int gemm_blocks = (N_NODES + 63) / 64;
    const int gather_blocks = (N_NODES * 32 + TB - 1) / TB;  // warp per node

    // ---- CSR build (once per replay) ----
    zero_counts_kernel<<<(N_NODES + TB - 1) / TB, TB>>>();
    hist_kernel<<<(N_EDGES + TB - 1) / TB, TB>>>(ei);
    scan_kernel<<<1, 1024>>>();
    fill_kernel<<<(N_EDGES + TB - 1) / TB, TB>>>(ei);

    // ---- layer 1 (Din=32) ----
    gather_kernel<DIN0><<<gather_blocks, TB>>>(x, aggbuf);
    gemm_kernel<DIN0, true><<<gemm_blocks, GB>>>(
        aggbuf, w_in[0], b_in[0], gam[0], bet[0], rme[0], rva[0], zbuf);
    gemm_kernel<HID, false><<<gemm_blocks, GB>>>(
        zbuf, w_out[0], b_out[0], nullptr, nullptr, nullptr, nullptr, hbuf);

    // ---- layer 2 ----
    gather_kernel<HID><<<gather_blocks, TB>>>(hbuf, aggbuf);
    gemm_kernel<HID, true><<<gemm_blocks, GB>>>(
        aggbuf, w_in[1], b_in[1], gam[1], bet[1], rme[1], rva[1], zbuf);
    gemm_kernel<HID, false><<<gemm_blocks, GB>>>(
        zbuf, w_out[1], b_out[1], nullptr, nullptr, nullptr, nullptr, hbuf);

    // ---- layer 3 ----
    gather_kernel<HID><<<gather_blocks, TB>>>(hbuf, aggbuf);
    gemm_kernel<HID, true><<<gemm_blocks, GB>>>(
        aggbuf, w_in[2], b_in[2], gam[2], bet[2], rme[2], rva[2], zbuf);
    gemm_kernel<HID, false><<<gemm_blocks, GB>>>(
        zbuf, w_out[2], b_out[2], nullptr, nullptr, nullptr, nullptr, hbuf);

    // ---- pooling + head ----
    pool_kernel<<<N_GRAPHS, 96>>>(bat, poolbuf);
    head_kernel<<<1, 256>>>(rtg, head_w, head_b, poolbuf, out);
}